// round 11
// baseline (speedup 1.0000x reference)
#include <cuda_runtime.h>

// TriplesDistances: B=16, N=512, A=1024
// inputs: positions f32 [B,N,3]; neighbors_j/k int32 [B,N,A]
// out layout: [r_ij | r_ik | r_jk], each B*N*A float32
#define NB 16
#define NN 512
#define NA 1024
#define THREADS 256
#define ROWS 4                    // rows per work item
#define NITEMS (NB * NN / ROWS)   // 2048 work items
#define NCTAS 912                 // 152 SMs * 6 CTAs: single resident wave

#define TOTAL (NB * NN * NA)      // 8388608, fits int32

__device__ __forceinline__ float dist3(float2 axy, float az, float2 bxy, float bz) {
    float dx = axy.x - bxy.x;
    float dy = axy.y - bxy.y;
    float dz = az - bz;
    float s = fmaf(dx, dx, fmaf(dy, dy, dz * dz));
    float r = s * rsqrtf(s);      // == sqrt(s)
    return (s > 0.0f) ? r : 0.0f;
}

__global__ __launch_bounds__(THREADS, 6)
void TriplesDistances_kernel(const float* __restrict__ pos,
                             const int* __restrict__ nj,
                             const int* __restrict__ nk,
                             float* __restrict__ out) {
    __shared__ float2 spxy[NN];  // 4 KB
    __shared__ float  spz[NN];   // 2 KB

    const unsigned t = threadIdx.x;
    const unsigned a0 = t * 4u;

    // Balanced contiguous chunk of work items for this CTA
    const unsigned c     = blockIdx.x;
    const unsigned start = (c * NITEMS) / NCTAS;
    const unsigned end   = ((c + 1) * NITEMS) / NCTAS;

    unsigned prev_b = 0xFFFFFFFFu;

    for (unsigned w = start; w < end; ++w) {
        const unsigned b  = w >> 7;            // 128 items per batch
        const unsigned n0 = (w & 127u) * ROWS;
        const unsigned base0 = (b * NN + n0) * NA + a0;   // 32-bit safe

        // Row-0 index loads first: DRAM latency overlaps (re)staging
        int4 j4 = __ldcs(reinterpret_cast<const int4*>(nj + base0));
        int4 k4 = __ldcs(reinterpret_cast<const int4*>(nk + base0));

        // (Re)stage positions only when the batch changes
        if (b != prev_b) {
            if (prev_b != 0xFFFFFFFFu) __syncthreads();  // drain readers of old batch
            const float* pb = pos + b * (NN * 3);
            #pragma unroll
            for (unsigned i = t; i < NN; i += THREADS) {
                float x = pb[i * 3 + 0];
                float y = pb[i * 3 + 1];
                float z = pb[i * 3 + 2];
                spxy[i] = make_float2(x, y);
                spz[i]  = z;
            }
            __syncthreads();
            prev_b = b;
        }

        #pragma unroll
        for (unsigned r = 0; r < ROWS; r++) {
            const unsigned base = base0 + r * NA;
            const int4 jc = j4, kc = k4;

            // Prefetch next row's indices while current gathers are in flight
            if (r + 1 < ROWS) {
                j4 = __ldcs(reinterpret_cast<const int4*>(nj + base + NA));
                k4 = __ldcs(reinterpret_cast<const int4*>(nk + base + NA));
            }

            const float2 pixy = spxy[n0 + r];
            const float  piz  = spz[n0 + r];

            float4 rij, rik, rjk;

            // Single-element pipeline: one (pj, pk) pair live at a time
            {
                float2 pj = spxy[jc.x]; float pjz = spz[jc.x];
                float2 pk = spxy[kc.x]; float pkz = spz[kc.x];
                rij.x = dist3(pj, pjz, pixy, piz);
                rik.x = dist3(pk, pkz, pixy, piz);
                rjk.x = dist3(pj, pjz, pk, pkz);
            }
            {
                float2 pj = spxy[jc.y]; float pjz = spz[jc.y];
                float2 pk = spxy[kc.y]; float pkz = spz[kc.y];
                rij.y = dist3(pj, pjz, pixy, piz);
                rik.y = dist3(pk, pkz, pixy, piz);
                rjk.y = dist3(pj, pjz, pk, pkz);
            }
            {
                float2 pj = spxy[jc.z]; float pjz = spz[jc.z];
                float2 pk = spxy[kc.z]; float pkz = spz[kc.z];
                rij.z = dist3(pj, pjz, pixy, piz);
                rik.z = dist3(pk, pkz, pixy, piz);
                rjk.z = dist3(pj, pjz, pk, pkz);
            }
            {
                float2 pj = spxy[jc.w]; float pjz = spz[jc.w];
                float2 pk = spxy[kc.w]; float pkz = spz[kc.w];
                rij.w = dist3(pj, pjz, pixy, piz);
                rik.w = dist3(pk, pkz, pixy, piz);
                rjk.w = dist3(pj, pjz, pk, pkz);
            }

            // Wide streaming stores (minimal LSU issue cycles)
            __stcs(reinterpret_cast<float4*>(out + base),              rij);
            __stcs(reinterpret_cast<float4*>(out + TOTAL + base),      rik);
            __stcs(reinterpret_cast<float4*>(out + 2u * TOTAL + base), rjk);
        }
    }
}

extern "C" void kernel_launch(void* const* d_in, const int* in_sizes, int n_in,
                              void* d_out, int out_size) {
    const float* pos = (const float*)d_in[0];
    const int*   nj  = (const int*)d_in[1];
    const int*   nk  = (const int*)d_in[2];
    float* out = (float*)d_out;

    dim3 grid(NCTAS);
    TriplesDistances_kernel<<<grid, THREADS>>>(pos, nj, nk, out);
}

// round 12
// speedup vs baseline: 1.1282x; 1.1282x over previous
#include <cuda_runtime.h>

// TriplesDistances: B=16, N=512, A=1024
// inputs: positions f32 [B,N,3]; neighbors_j/k int32 [B,N,A]
// out layout: [r_ij | r_ik | r_jk], each B*N*A float32
#define NB 16
#define NN 512
#define NA 1024
#define THREADS 256
#define ROWS 4   // rows (n values) per block, same batch

#define TOTAL (NB * NN * NA)   // 8388608, fits int32

__device__ __forceinline__ float dist3(float2 axy, float az, float2 bxy, float bz) {
    float dx = axy.x - bxy.x;
    float dy = axy.y - bxy.y;
    float dz = az - bz;
    float s = fmaf(dx, dx, fmaf(dy, dy, dz * dz));
    float r = s * rsqrtf(s);      // == sqrt(s)
    return (s > 0.0f) ? r : 0.0f;
}

__global__ __launch_bounds__(THREADS, 5)
void TriplesDistances_kernel(const float* __restrict__ pos,
                             const int* __restrict__ nj,
                             const int* __restrict__ nk,
                             float* __restrict__ out) {
    __shared__ float2 spxy[NN];  // 4 KB
    __shared__ float  spz[NN];   // 2 KB

    const unsigned blk = blockIdx.x;                 // 0 .. NB*NN/ROWS-1
    const unsigned b   = blk / (NN / ROWS);          // batch
    const unsigned n0  = (blk % (NN / ROWS)) * ROWS; // first row in batch
    const unsigned t   = threadIdx.x;

    const unsigned a0    = t * 4u;
    const unsigned base0 = (b * NN + n0) * NA + a0;  // 32-bit safe

    // Row-0 index loads issued BEFORE staging: DRAM latency overlaps staging+sync
    int4 j4 = __ldcs(reinterpret_cast<const int4*>(nj + base0));
    int4 k4 = __ldcs(reinterpret_cast<const int4*>(nk + base0));

    // Cooperative stage of batch-b positions into smem (SoA)
    const float* pb = pos + b * (NN * 3);
    #pragma unroll
    for (unsigned i = t; i < NN; i += THREADS) {
        float x = pb[i * 3 + 0];
        float y = pb[i * 3 + 1];
        float z = pb[i * 3 + 2];
        spxy[i] = make_float2(x, y);
        spz[i]  = z;
    }
    __syncthreads();

    #pragma unroll
    for (unsigned r = 0; r < ROWS; r++) {
        const unsigned base = base0 + r * NA;
        const int4 jc = j4, kc = k4;

        // Prefetch next row's indices while current gathers are in flight
        if (r + 1 < ROWS) {
            j4 = __ldcs(reinterpret_cast<const int4*>(nj + base + NA));
            k4 = __ldcs(reinterpret_cast<const int4*>(nk + base + NA));
        }

        const float2 pixy = spxy[n0 + r];
        const float  piz  = spz[n0 + r];

        float4 rij, rik, rjk;

        // Two-element gather hoisting: 8 independent LDS in flight per group
        {
            float2 pj0 = spxy[jc.x]; float pj0z = spz[jc.x];
            float2 pk0 = spxy[kc.x]; float pk0z = spz[kc.x];
            float2 pj1 = spxy[jc.y]; float pj1z = spz[jc.y];
            float2 pk1 = spxy[kc.y]; float pk1z = spz[kc.y];
            rij.x = dist3(pj0, pj0z, pixy, piz);
            rik.x = dist3(pk0, pk0z, pixy, piz);
            rjk.x = dist3(pj0, pj0z, pk0, pk0z);
            rij.y = dist3(pj1, pj1z, pixy, piz);
            rik.y = dist3(pk1, pk1z, pixy, piz);
            rjk.y = dist3(pj1, pj1z, pk1, pk1z);
        }
        {
            float2 pj2 = spxy[jc.z]; float pj2z = spz[jc.z];
            float2 pk2 = spxy[kc.z]; float pk2z = spz[kc.z];
            float2 pj3 = spxy[jc.w]; float pj3z = spz[jc.w];
            float2 pk3 = spxy[kc.w]; float pk3z = spz[kc.w];
            rij.z = dist3(pj2, pj2z, pixy, piz);
            rik.z = dist3(pk2, pk2z, pixy, piz);
            rjk.z = dist3(pj2, pj2z, pk2, pk2z);
            rij.w = dist3(pj3, pj3z, pixy, piz);
            rik.w = dist3(pk3, pk3z, pixy, piz);
            rjk.w = dist3(pj3, pj3z, pk3, pk3z);
        }

        // Wide streaming stores (minimal LSU issue cycles)
        __stcs(reinterpret_cast<float4*>(out + base),              rij);
        __stcs(reinterpret_cast<float4*>(out + TOTAL + base),      rik);
        __stcs(reinterpret_cast<float4*>(out + 2u * TOTAL + base), rjk);
    }
}

extern "C" void kernel_launch(void* const* d_in, const int* in_sizes, int n_in,
                              void* d_out, int out_size) {
    const float* pos = (const float*)d_in[0];
    const int*   nj  = (const int*)d_in[1];
    const int*   nk  = (const int*)d_in[2];
    float* out = (float*)d_out;

    dim3 grid(NB * NN / ROWS);
    TriplesDistances_kernel<<<grid, THREADS>>>(pos, nj, nk, out);
}